// round 16
// baseline (speedup 1.0000x reference)
#include <cuda_runtime.h>
#include <cuda_bf16.h>
#include <cuda_fp16.h>
#include <stdint.h>
#include <math.h>

#define B_ROWS 65536
#define DIM    512
#define KTOT   512
#define BD     (B_ROWS * DIM)
#define EPSF   1e-15f
#define MAXN   0.996f
#define CLIPA  (1.0f - 1e-7f)
#define NCHUNK 4

static const int CHUNK_OFF[NCHUNK + 1] = {0, 4096, 32768, 61440, 65536};

// ------------------------------------------------------------------
// Static scratch (g_ub eliminated — u lives only in smem)
// ------------------------------------------------------------------
__device__ __align__(16) __nv_bfloat16 g_zb[DIM * KTOT];  // Zh^T [out j][512]
__device__ __align__(16) __half g_innh[BD];               // inner, fp16
__device__ float g_cu2[B_ROWS];
__device__ float g_x2c[B_ROWS];
__device__ __align__(16) float g_c1[DIM];
__device__ __align__(16) float g_c2[DIM];
__device__ __align__(16) float g_s2[DIM];

// ------------------------------------------------------------------
// Fast math (MUFU-based)
// ------------------------------------------------------------------
__device__ __forceinline__ float f_rcp(float x){ float y; asm("rcp.approx.f32 %0,%1;" : "=f"(y) : "f"(x)); return y; }
__device__ __forceinline__ float f_lg2(float x){ float y; asm("lg2.approx.f32 %0,%1;" : "=f"(y) : "f"(x)); return y; }
__device__ __forceinline__ float f_ex2(float x){ float y; asm("ex2.approx.f32 %0,%1;" : "=f"(y) : "f"(x)); return y; }
__device__ __forceinline__ float f_sqrt(float x){ float y; asm("sqrt.approx.f32 %0,%1;" : "=f"(y) : "f"(x)); return y; }

__device__ __forceinline__ float atanh_f(float x){
    return 0.34657359028f * f_lg2((1.f + x) * f_rcp(1.f - x));
}
__device__ __forceinline__ float tanh_f(float x){
    return 1.f - 2.f * f_rcp(f_ex2(x * 2.88539008178f) + 1.f);
}
__device__ __forceinline__ float sigmoid_f(float x){
    return f_rcp(1.f + f_ex2(-1.44269504089f * x));
}
__device__ __forceinline__ float sinh_asinh(float t, float s){
    float a = fabsf(t);
    float q = a + f_sqrt(fmaf(a, a, 1.f));
    float p = f_ex2(s * f_lg2(q));
    return copysignf(0.5f * (p - f_rcp(p)), t);
}

// ------------------------------------------------------------------
// Portable tensor-core primitives
// ------------------------------------------------------------------
__device__ __forceinline__ uint32_t s2u(const void* p){ return (uint32_t)__cvta_generic_to_shared(p); }

__device__ __forceinline__ void cp16(uint32_t dst, const void* src){
    asm volatile("cp.async.cg.shared.global [%0], [%1], 16;" :: "r"(dst), "l"(src));
}
__device__ __forceinline__ void cp_commit(){ asm volatile("cp.async.commit_group;" ::: "memory"); }
template<int N> __device__ __forceinline__ void cp_wait(){ asm volatile("cp.async.wait_group %0;" :: "n"(N) : "memory"); }

__device__ __forceinline__ void ldsm4(uint32_t* r, uint32_t addr){
    asm volatile("ldmatrix.sync.aligned.m8n8.x4.shared.b16 {%0,%1,%2,%3}, [%4];"
        : "=r"(r[0]),"=r"(r[1]),"=r"(r[2]),"=r"(r[3]) : "r"(addr));
}
__device__ __forceinline__ void mma16816(float* c, const uint32_t* a, uint32_t b0, uint32_t b1){
    asm volatile("mma.sync.aligned.m16n8k16.row.col.f32.bf16.bf16.f32 "
        "{%0,%1,%2,%3}, {%4,%5,%6,%7}, {%8,%9}, {%0,%1,%2,%3};"
        : "+f"(c[0]),"+f"(c[1]),"+f"(c[2]),"+f"(c[3])
        : "r"(a[0]),"r"(a[1]),"r"(a[2]),"r"(a[3]), "r"(b0),"r"(b1));
}

// ------------------------------------------------------------------
// Kernel 1: z stats + transposed bf16 z
// ------------------------------------------------------------------
__global__ void prep_cols(const float* __restrict__ z, const float* __restrict__ bias){
    __shared__ float sb[4];
    int j = blockIdx.x, t = threadIdx.x;
    float s = 0.f;
    for (int i = t; i < DIM; i += 128){
        float v = z[i * DIM + j];
        s += v * v;
        g_zb[j * KTOT + i] = __float2bfloat16(v);
    }
#pragma unroll
    for (int o = 16; o; o >>= 1) s += __shfl_down_sync(0xffffffffu, s, o);
    if ((t & 31) == 0) sb[t >> 5] = s;
    __syncthreads();
    if (t == 0){
        float tot = sb[0] + sb[1] + sb[2] + sb[3];
        float zn = sqrtf(fmaxf(tot, EPSF));
        float tb = 2.f * bias[j];
        g_c1[j] = 2.f * coshf(tb) / zn;
        g_c2[j] = sinhf(tb);
        g_s2[j] = 2.f * zn;
    }
}

// ------------------------------------------------------------------
// Kernel 2 (FUSED prep+gemm): 64 rows/CTA.
// Phase 1: u computed straight into swizzled smem A (+ o2, cu2, x2c).
// Phase 2: B-only cp.async pipeline; 4 N-blocks from the static A tile.
// 112 KB smem -> 2 CTAs/SM, so prep (MUFU) of one CTA overlaps the
// tensor phase of its SM-mate.
// ------------------------------------------------------------------
#define FBM 64
#define FB_STAGE 16384                       /* 128 n-rows x 128 B */
#define FSM_A    65536                       /* 64 rows x 1024 B   */
#define FSM_TOT  (FSM_A + 3 * FB_STAGE)      /* 114688 */
#define NQ 32                                /* 4 n-blocks x 8 kt  */

__global__ void __launch_bounds__(256, 2) fused_pg(
        const float* __restrict__ xc_g,
        const float* __restrict__ xp_g,
        float* __restrict__ out,
        int row0){
    extern __shared__ __align__(128) char sm[];
    uint32_t sb = s2u(sm);
    int tid = threadIdx.x;
    int wid = tid >> 5, l = tid & 31;
    int m0 = row0 + blockIdx.x * FBM;

    // ================= phase 1: prep into smem A =================
#pragma unroll 1
    for (int it = 0; it < 8; it++){
        int rl  = wid * 8 + it;          // local row 0..63
        int row = m0 + rl;
        const float4* xc4 = (const float4*)(xc_g + (size_t)row * DIM);
        const float4* xp4 = (const float4*)(xp_g + (size_t)row * DIM);

        float4 xc[4], xp[4];
        float px2 = 0.f, py2 = 0.f, pxy = 0.f;
#pragma unroll
        for (int i = 0; i < 4; i++){
            xc[i] = xc4[i * 32 + l];
            xp[i] = xp4[i * 32 + l];
            px2 += xp[i].x*xp[i].x + xp[i].y*xp[i].y + xp[i].z*xp[i].z + xp[i].w*xp[i].w;
            py2 += xc[i].x*xc[i].x + xc[i].y*xc[i].y + xc[i].z*xc[i].z + xc[i].w*xc[i].w;
            pxy += xp[i].x*xc[i].x + xp[i].y*xc[i].y + xp[i].z*xc[i].z + xp[i].w*xc[i].w;
        }
#pragma unroll
        for (int o = 16; o; o >>= 1){
            px2 += __shfl_xor_sync(0xffffffffu, px2, o);
            py2 += __shfl_xor_sync(0xffffffffu, py2, o);
            pxy += __shfl_xor_sync(0xffffffffu, pxy, o);
        }
        float fA = 1.f - 2.f * pxy + py2;
        float fB = 1.f - px2;
        float invden = f_rcp(fmaxf(1.f - 2.f * pxy + px2 * py2, EPSF));

        float4 sub[4];
        float psn2 = 0.f;
#pragma unroll
        for (int i = 0; i < 4; i++){
            sub[i].x = (fB * xc[i].x - fA * xp[i].x) * invden;
            sub[i].y = (fB * xc[i].y - fA * xp[i].y) * invden;
            sub[i].z = (fB * xc[i].z - fA * xp[i].z) * invden;
            sub[i].w = (fB * xc[i].w - fA * xp[i].w) * invden;
            psn2 += sub[i].x*sub[i].x + sub[i].y*sub[i].y + sub[i].z*sub[i].z + sub[i].w*sub[i].w;
        }
#pragma unroll
        for (int o = 16; o; o >>= 1) psn2 += __shfl_xor_sync(0xffffffffu, psn2, o);
        float sn2 = psn2;
        float sn  = f_sqrt(fmaxf(sn2, EPSF));
        float c   = fmaxf(fB, EPSF) * atanh_f(fminf(sn, CLIPA)) * f_rcp(sn);
        float un  = f_sqrt(fmaxf(c * c * sn2, EPSF));
        float s   = tanh_f(un) * c * f_rcp(un);

        float nxc = f_sqrt(fmaxf(py2, EPSF));
        float fxc = (nxc > MAXN) ? MAXN * f_rcp(nxc) : 1.f;
        float4* o2p = (float4*)(out + (size_t)BD + (size_t)row * DIM);

#pragma unroll
        for (int i = 0; i < 4; i++){
            float u0 = s*sub[i].x, u1 = s*sub[i].y, u2 = s*sub[i].z, u3 = s*sub[i].w;
            __nv_bfloat16 h0=__float2bfloat16(u0), h1=__float2bfloat16(u1),
                          h2=__float2bfloat16(u2), h3=__float2bfloat16(u3);
            uint2 hv;
            hv.x = (uint32_t)__bfloat16_as_ushort(h0) | ((uint32_t)__bfloat16_as_ushort(h1) << 16);
            hv.y = (uint32_t)__bfloat16_as_ushort(h2) | ((uint32_t)__bfloat16_as_ushort(h3) << 16);
            // swizzled store into A tile: chunk = i*16 + (l>>1), XOR low 3 bits by row
            int chunk = i * 16 + (l >> 1);
            int swc   = chunk ^ (rl & 7);
            *(uint2*)(sm + rl * 1024 + swc * 16 + (l & 1) * 8) = hv;
            float4 o2;
            o2.x = fxc * xc[i].x; o2.y = fxc * xc[i].y;
            o2.z = fxc * xc[i].z; o2.w = fxc * xc[i].w;
            o2p[i * 32 + l] = o2;
        }
        if (l == 0){
            g_cu2[row] = s * s * sn2;
            g_x2c[row] = py2;
        }
    }
    __syncthreads();

    // ================= phase 2: gemm from static A tile =================
    const char* gB = (const char*)g_zb;
    int wm = wid & 1;           // 2 warps over M (32 rows)
    int wn = wid >> 1;          // 4 warps over N (32 cols)
    int lrow = l & 15;
    int khalf = l >> 4;
    int erow = l >> 2;
    int ecol = (l & 3) * 2;

    float acc[2][4][4];

#define BLOAD(st, q) do {                                                      \
        uint32_t base_ = sb + FSM_A + (st) * FB_STAGE;                         \
        int nb_ = (q) >> 3, kt_ = (q) & 7;                                     \
        size_t k0_ = (size_t)kt_ * 64;                                         \
        _Pragma("unroll")                                                      \
        for (int it = 0; it < 4; it++){                                        \
            int idx_ = it * 256 + tid;                                         \
            int r_ = idx_ >> 3, c_ = idx_ & 7;                                 \
            cp16(base_ + r_ * 128 + ((c_ ^ (r_ & 7)) << 4),                    \
                 gB + ((size_t)(nb_ * 128 + r_) * KTOT + k0_) * 2 + (c_ << 4));\
        }                                                                      \
    } while (0)

    BLOAD(0, 0); cp_commit();
    BLOAD(1, 1); cp_commit();

#pragma unroll 1
    for (int q = 0; q < NQ; q++){
        int nb = q >> 3, kt = q & 7;
        if (kt == 0){
#pragma unroll
            for (int i=0;i<2;i++)
#pragma unroll
                for (int j=0;j<4;j++)
#pragma unroll
                    for (int k=0;k<4;k++) acc[i][j][k] = 0.f;
        }
        cp_wait<1>();
        __syncthreads();
        uint32_t bBase = sb + FSM_A + (q % 3) * FB_STAGE;
#pragma unroll
        for (int ks = 0; ks < 4; ks++){
            int c16k = kt * 8 + ks * 2 + khalf;   // A chunk (global k)
            int c16b = ks * 2 + khalf;            // B chunk (within stage)
            uint32_t a[2][4], bb[2][4];
#pragma unroll
            for (int mi = 0; mi < 2; mi++){
                int row = wm * 32 + mi * 16 + lrow;
                ldsm4(a[mi], sb + row * 1024 + ((c16k ^ (row & 7)) << 4));
            }
#pragma unroll
            for (int j = 0; j < 2; j++){
                int row = wn * 32 + j * 16 + lrow;
                ldsm4(bb[j], bBase + row * 128 + ((c16b ^ (row & 7)) << 4));
            }
#pragma unroll
            for (int mi = 0; mi < 2; mi++)
#pragma unroll
                for (int ni = 0; ni < 4; ni++)
                    mma16816(acc[mi][ni], a[mi], bb[ni >> 1][ni & 1], bb[ni >> 1][(ni & 1) + 2]);
        }
        if (q + 2 < NQ){ BLOAD((q + 2) % 3, q + 2); }
        cp_commit();
        __syncthreads();

        if (kt == 7){
#pragma unroll
            for (int mi = 0; mi < 2; mi++){
#pragma unroll
                for (int ni = 0; ni < 4; ni++){
                    int r = m0 + wm * 32 + mi * 16 + erow;
                    int cc = nb * 128 + wn * 32 + ni * 8 + ecol;
                    __half* p = g_innh + (size_t)r * DIM + cc;
                    *(__half2*)p             = __floats2half2_rn(acc[mi][ni][0], acc[mi][ni][1]);
                    *(__half2*)(p + 8 * DIM) = __floats2half2_rn(acc[mi][ni][2], acc[mi][ni][3]);
                }
            }
        }
    }
}

// ------------------------------------------------------------------
// Kernel 3: warp-per-row epilogue (chunked), o1 only, fp16 inner
// ------------------------------------------------------------------
__global__ void __launch_bounds__(256) finish_rows(const float* __restrict__ xc_g,
                                                   const float* __restrict__ alpha_p,
                                                   const float* __restrict__ step_p,
                                                   float* __restrict__ out,
                                                   int row0){
    int row = row0 + blockIdx.x * 8 + (threadIdx.x >> 5);
    int l   = threadIdx.x & 31;
    const uint2* in2 = (const uint2*)(g_innh + (size_t)row * DIM);
    const float4* xc4 = (const float4*)(xc_g + (size_t)row * DIM);
    const float4* c14 = (const float4*)g_c1;
    const float4* c24 = (const float4*)g_c2;
    const float4* s24 = (const float4*)g_s2;

    float cu2 = g_cu2[row], x2 = g_x2c[row];
    float invdn = f_rcp(fmaxf(1.f - cu2, EPSF));
    float op = 1.f + cu2;

    float w[16], xcv[16];
    float pw2 = 0.f, pxw = 0.f;
#pragma unroll
    for (int i = 0; i < 4; i++){
        int c4 = i * 32 + l;
        uint2 hv = in2[c4];
        float2 f01 = __half22float2(*(__half2*)&hv.x);
        float2 f23 = __half22float2(*(__half2*)&hv.y);
        float4 xv = xc4[c4], a = c14[c4], b = c24[c4], sv = s24[c4];
        float t0 = (f01.x * a.x - op * b.x) * invdn;
        float t1 = (f01.y * a.y - op * b.y) * invdn;
        float t2 = (f23.x * a.z - op * b.z) * invdn;
        float t3 = (f23.y * a.w - op * b.w) * invdn;
        float w0 = sinh_asinh(t0, sv.x), w1 = sinh_asinh(t1, sv.y);
        float w2 = sinh_asinh(t2, sv.z), w3 = sinh_asinh(t3, sv.w);
        w[i*4+0]=w0; w[i*4+1]=w1; w[i*4+2]=w2; w[i*4+3]=w3;
        xcv[i*4+0]=xv.x; xcv[i*4+1]=xv.y; xcv[i*4+2]=xv.z; xcv[i*4+3]=xv.w;
        pw2 = fmaf(w0,w0, fmaf(w1,w1, fmaf(w2,w2, fmaf(w3,w3, pw2))));
        pxw = fmaf(xv.x,w0, fmaf(xv.y,w1, fmaf(xv.z,w2, fmaf(xv.w,w3, pxw))));
    }
#pragma unroll
    for (int o = 16; o; o >>= 1){
        pw2 += __shfl_xor_sync(0xffffffffu, pw2, o);
        pxw += __shfl_xor_sync(0xffffffffu, pxw, o);
    }
    float w2s = pw2, xw = pxw;

    float gg  = 1.f + f_sqrt(1.f + w2s);
    float rg  = f_rcp(gg);
    float yn  = f_sqrt(fmaxf(w2s * rg * rg, EPSF));
    float kv  = atanh_f(fminf(yn, CLIPA)) * f_rcp(yn);
    float step = sigmoid_f(step_p[0]);
    float m0s = step * kv * rg;
    float un  = f_sqrt(fmaxf(m0s * m0s * w2s, EPSF));
    float lam = 2.f * f_rcp(fmaxf(1.f - x2, EPSF));
    float mt  = tanh_f(0.5f * lam * un) * m0s * f_rcp(un);

    float t2s = mt * mt * w2s;
    float xt  = mt * xw;
    float pp  = 1.f + 2.f * xt + t2s;
    float qq  = 1.f - x2;
    float id2 = f_rcp(fmaxf(1.f + 2.f * xt + x2 * t2s, EPSF));
    float a1  = pp * id2, b1 = qq * mt * id2;

    float nxu2 = a1*a1*x2 + 2.f*a1*b1*xw + b1*b1*w2s;
    float nxu  = f_sqrt(fmaxf(nxu2, EPSF));
    float fxu  = (nxu > MAXN) ? MAXN * f_rcp(nxu) : 1.f;
    a1 *= fxu; b1 *= fxu;
    float nxup = fminf(nxu, MAXN);

    float nxc  = f_sqrt(fmaxf(x2, EPSF));
    float fxc  = (nxc > MAXN) ? MAXN * f_rcp(nxc) : 1.f;
    float nxcp = fminf(nxc, MAXN);

    float aa  = sigmoid_f(alpha_p[0]);
    float th1 = tanh_f(aa * atanh_f(fminf(nxcp, CLIPA)));
    float A1  = th1 * f_rcp(nxcp) * fxc;
    float th2 = tanh_f((1.f - aa) * atanh_f(fminf(nxup, CLIPA)));
    float r2  = th2 * f_rcp(nxup);
    float A2  = r2 * a1, B2 = r2 * b1;

    float x2m = th1 * th1, y2m = th2 * th2;
    float xym = A1 * (A2 * x2 + B2 * xw);
    float P   = 1.f + 2.f * xym + y2m;
    float Q   = 1.f - x2m;
    float id3 = f_rcp(fmaxf(1.f + 2.f * xym + x2m * y2m, EPSF));
    float CA  = (P * A1 + Q * A2) * id3;
    float CB  = (Q * B2) * id3;

    float nn2 = CA*CA*x2 + 2.f*CA*CB*xw + CB*CB*w2s;
    float nn  = f_sqrt(fmaxf(nn2, EPSF));
    float fo  = (nn > MAXN) ? MAXN * f_rcp(nn) : 1.f;
    CA *= fo; CB *= fo;

    float4* o1p = (float4*)(out + (size_t)row * DIM);
#pragma unroll
    for (int i = 0; i < 4; i++){
        int c4 = i * 32 + l;
        float4 o1;
        o1.x = CA*xcv[i*4+0] + CB*w[i*4+0];
        o1.y = CA*xcv[i*4+1] + CB*w[i*4+1];
        o1.z = CA*xcv[i*4+2] + CB*w[i*4+2];
        o1.w = CA*xcv[i*4+3] + CB*w[i*4+3];
        o1p[c4] = o1;
    }
}

// ------------------------------------------------------------------
// Launch: 2 streams, uneven chunks.
//   s3: prep_cols, then finish chunks
//   s1: fused prep+gemm chunks (waits eC)
// ------------------------------------------------------------------
extern "C" void kernel_launch(void* const* d_in, const int* in_sizes, int n_in,
                              void* d_out, int out_size) {
    const float* xc    = (const float*)d_in[0];
    const float* xp    = (const float*)d_in[1];
    const float* z     = (const float*)d_in[2];
    const float* bias  = (const float*)d_in[3];
    const float* alpha = (const float*)d_in[4];
    const float* stepz = (const float*)d_in[5];
    float* out = (float*)d_out;

    static cudaStream_t s1, s3;
    static cudaEvent_t eRoot, eC, eG[NCHUNK], eJ1, eJ3;
    static int inited = 0;
    if (!inited){
        cudaStreamCreateWithFlags(&s1, cudaStreamNonBlocking);
        cudaStreamCreateWithFlags(&s3, cudaStreamNonBlocking);
        cudaEventCreateWithFlags(&eRoot, cudaEventDisableTiming);
        cudaEventCreateWithFlags(&eC, cudaEventDisableTiming);
        for (int m = 0; m < NCHUNK; m++)
            cudaEventCreateWithFlags(&eG[m], cudaEventDisableTiming);
        cudaEventCreateWithFlags(&eJ1, cudaEventDisableTiming);
        cudaEventCreateWithFlags(&eJ3, cudaEventDisableTiming);
        cudaFuncSetAttribute(fused_pg, cudaFuncAttributeMaxDynamicSharedMemorySize, FSM_TOT);
        inited = 1;
    }

    // fork
    cudaEventRecord(eRoot, 0);
    cudaStreamWaitEvent(s1, eRoot, 0);
    cudaStreamWaitEvent(s3, eRoot, 0);

    // s3: column prep
    prep_cols<<<DIM, 128, 0, s3>>>(z, bias);
    cudaEventRecord(eC, s3);
    cudaStreamWaitEvent(s1, eC, 0);

    // s1: fused prep+gemm per chunk
    for (int m = 0; m < NCHUNK; m++){
        int r0 = CHUNK_OFF[m], nr = CHUNK_OFF[m + 1] - r0;
        fused_pg<<<nr / FBM, 256, FSM_TOT, s1>>>(xc, xp, out, r0);
        cudaEventRecord(eG[m], s1);
    }

    // s3: finish per chunk
    for (int m = 0; m < NCHUNK; m++){
        int r0 = CHUNK_OFF[m], nr = CHUNK_OFF[m + 1] - r0;
        cudaStreamWaitEvent(s3, eG[m], 0);
        finish_rows<<<nr / 8, 256, 0, s3>>>(xc, alpha, stepz, out, r0);
    }

    // join
    cudaEventRecord(eJ1, s1);
    cudaEventRecord(eJ3, s3);
    cudaStreamWaitEvent(0, eJ1, 0);
    cudaStreamWaitEvent(0, eJ3, 0);
}

// round 17
// speedup vs baseline: 1.2293x; 1.2293x over previous
#include <cuda_runtime.h>
#include <cuda_bf16.h>
#include <cuda_fp16.h>
#include <stdint.h>
#include <math.h>

#define B_ROWS 65536
#define DIM    512
#define KTOT   512             /* single bf16 GEMM: Uh @ Zh^T */
#define BD     (B_ROWS * DIM)
#define EPSF   1e-15f
#define MAXN   0.996f
#define CLIPA  (1.0f - 1e-7f)
#define NCHUNK 6

/* finer uneven chunks: small fill + drain, fat middle */
static const int CHUNK_OFF[NCHUNK + 1] =
    {0, 4096, 20480, 36864, 53248, 61440, 65536};

// ------------------------------------------------------------------
// Static scratch (inner fp16)
// ------------------------------------------------------------------
__device__ __align__(16) __nv_bfloat16 g_ub[(size_t)B_ROWS * KTOT]; // Uh [B][512]
__device__ __align__(16) __nv_bfloat16 g_zb[DIM * KTOT];            // Zh^T [out j][512]
__device__ __align__(16) __half g_innh[BD];                          // inner, fp16
__device__ float g_cu2[B_ROWS];
__device__ float g_x2c[B_ROWS];
__device__ __align__(16) float g_c1[DIM];
__device__ __align__(16) float g_c2[DIM];
__device__ __align__(16) float g_s2[DIM];

// ------------------------------------------------------------------
// Fast math (MUFU-based)
// ------------------------------------------------------------------
__device__ __forceinline__ float f_rcp(float x){ float y; asm("rcp.approx.f32 %0,%1;" : "=f"(y) : "f"(x)); return y; }
__device__ __forceinline__ float f_lg2(float x){ float y; asm("lg2.approx.f32 %0,%1;" : "=f"(y) : "f"(x)); return y; }
__device__ __forceinline__ float f_ex2(float x){ float y; asm("ex2.approx.f32 %0,%1;" : "=f"(y) : "f"(x)); return y; }
__device__ __forceinline__ float f_sqrt(float x){ float y; asm("sqrt.approx.f32 %0,%1;" : "=f"(y) : "f"(x)); return y; }

__device__ __forceinline__ float atanh_f(float x){
    return 0.34657359028f * f_lg2((1.f + x) * f_rcp(1.f - x));
}
__device__ __forceinline__ float tanh_f(float x){
    return 1.f - 2.f * f_rcp(f_ex2(x * 2.88539008178f) + 1.f);
}
__device__ __forceinline__ float sigmoid_f(float x){
    return f_rcp(1.f + f_ex2(-1.44269504089f * x));
}
__device__ __forceinline__ float sinh_asinh(float t, float s){
    float a = fabsf(t);
    float q = a + f_sqrt(fmaf(a, a, 1.f));
    float p = f_ex2(s * f_lg2(q));
    return copysignf(0.5f * (p - f_rcp(p)), t);
}

// ------------------------------------------------------------------
// Portable tensor-core primitives
// ------------------------------------------------------------------
__device__ __forceinline__ uint32_t s2u(const void* p){ return (uint32_t)__cvta_generic_to_shared(p); }

__device__ __forceinline__ void cp16(uint32_t dst, const void* src){
    asm volatile("cp.async.cg.shared.global [%0], [%1], 16;" :: "r"(dst), "l"(src));
}
__device__ __forceinline__ void cp_commit(){ asm volatile("cp.async.commit_group;" ::: "memory"); }
template<int N> __device__ __forceinline__ void cp_wait(){ asm volatile("cp.async.wait_group %0;" :: "n"(N) : "memory"); }

__device__ __forceinline__ void ldsm4(uint32_t* r, uint32_t addr){
    asm volatile("ldmatrix.sync.aligned.m8n8.x4.shared.b16 {%0,%1,%2,%3}, [%4];"
        : "=r"(r[0]),"=r"(r[1]),"=r"(r[2]),"=r"(r[3]) : "r"(addr));
}
__device__ __forceinline__ void mma16816(float* c, const uint32_t* a, uint32_t b0, uint32_t b1){
    asm volatile("mma.sync.aligned.m16n8k16.row.col.f32.bf16.bf16.f32 "
        "{%0,%1,%2,%3}, {%4,%5,%6,%7}, {%8,%9}, {%0,%1,%2,%3};"
        : "+f"(c[0]),"+f"(c[1]),"+f"(c[2]),"+f"(c[3])
        : "r"(a[0]),"r"(a[1]),"r"(a[2]),"r"(a[3]), "r"(b0),"r"(b1));
}

// ------------------------------------------------------------------
// Kernel 1: z stats + transposed bf16 z
// ------------------------------------------------------------------
__global__ void prep_cols(const float* __restrict__ z, const float* __restrict__ bias){
    __shared__ float sb[4];
    int j = blockIdx.x, t = threadIdx.x;
    float s = 0.f;
    for (int i = t; i < DIM; i += 128){
        float v = z[i * DIM + j];
        s += v * v;
        g_zb[j * KTOT + i] = __float2bfloat16(v);
    }
#pragma unroll
    for (int o = 16; o; o >>= 1) s += __shfl_down_sync(0xffffffffu, s, o);
    if ((t & 31) == 0) sb[t >> 5] = s;
    __syncthreads();
    if (t == 0){
        float tot = sb[0] + sb[1] + sb[2] + sb[3];
        float zn = sqrtf(fmaxf(tot, EPSF));
        float tb = 2.f * bias[j];
        g_c1[j] = 2.f * coshf(tb) / zn;
        g_c2[j] = sinhf(tb);
        g_s2[j] = 2.f * zn;
    }
}

// ------------------------------------------------------------------
// Kernel 2: warp-per-row (chunked): u -> bf16, AND o2 = projx(xc)
// ------------------------------------------------------------------
__global__ void __launch_bounds__(256) prep_rows(const float* __restrict__ xc_g,
                                                 const float* __restrict__ xp_g,
                                                 float* __restrict__ out,
                                                 int row0){
    int row = row0 + blockIdx.x * 8 + (threadIdx.x >> 5);
    int l   = threadIdx.x & 31;
    const float4* xc4 = (const float4*)(xc_g + (size_t)row * DIM);
    const float4* xp4 = (const float4*)(xp_g + (size_t)row * DIM);

    float4 xc[4], xp[4];
    float px2 = 0.f, py2 = 0.f, pxy = 0.f;
#pragma unroll
    for (int i = 0; i < 4; i++){
        xc[i] = xc4[i * 32 + l];
        xp[i] = xp4[i * 32 + l];
        px2 += xp[i].x*xp[i].x + xp[i].y*xp[i].y + xp[i].z*xp[i].z + xp[i].w*xp[i].w;
        py2 += xc[i].x*xc[i].x + xc[i].y*xc[i].y + xc[i].z*xc[i].z + xc[i].w*xc[i].w;
        pxy += xp[i].x*xc[i].x + xp[i].y*xc[i].y + xp[i].z*xc[i].z + xp[i].w*xc[i].w;
    }
#pragma unroll
    for (int o = 16; o; o >>= 1){
        px2 += __shfl_xor_sync(0xffffffffu, px2, o);
        py2 += __shfl_xor_sync(0xffffffffu, py2, o);
        pxy += __shfl_xor_sync(0xffffffffu, pxy, o);
    }
    float fA = 1.f - 2.f * pxy + py2;
    float fB = 1.f - px2;
    float invden = f_rcp(fmaxf(1.f - 2.f * pxy + px2 * py2, EPSF));

    float4 sub[4];
    float psn2 = 0.f;
#pragma unroll
    for (int i = 0; i < 4; i++){
        sub[i].x = (fB * xc[i].x - fA * xp[i].x) * invden;
        sub[i].y = (fB * xc[i].y - fA * xp[i].y) * invden;
        sub[i].z = (fB * xc[i].z - fA * xp[i].z) * invden;
        sub[i].w = (fB * xc[i].w - fA * xp[i].w) * invden;
        psn2 += sub[i].x*sub[i].x + sub[i].y*sub[i].y + sub[i].z*sub[i].z + sub[i].w*sub[i].w;
    }
#pragma unroll
    for (int o = 16; o; o >>= 1) psn2 += __shfl_xor_sync(0xffffffffu, psn2, o);
    float sn2 = psn2;
    float sn  = f_sqrt(fmaxf(sn2, EPSF));
    float c   = fmaxf(fB, EPSF) * atanh_f(fminf(sn, CLIPA)) * f_rcp(sn);
    float un  = f_sqrt(fmaxf(c * c * sn2, EPSF));
    float s   = tanh_f(un) * c * f_rcp(un);

    float nxc = f_sqrt(fmaxf(py2, EPSF));
    float fxc = (nxc > MAXN) ? MAXN * f_rcp(nxc) : 1.f;
    float4* o2p = (float4*)(out + (size_t)BD + (size_t)row * DIM);

    uint2* ub = (uint2*)(g_ub + (size_t)row * KTOT);
#pragma unroll
    for (int i = 0; i < 4; i++){
        float u0 = s*sub[i].x, u1 = s*sub[i].y, u2 = s*sub[i].z, u3 = s*sub[i].w;
        __nv_bfloat16 h0=__float2bfloat16(u0), h1=__float2bfloat16(u1),
                      h2=__float2bfloat16(u2), h3=__float2bfloat16(u3);
        uint2 hv;
        hv.x = (uint32_t)__bfloat16_as_ushort(h0) | ((uint32_t)__bfloat16_as_ushort(h1) << 16);
        hv.y = (uint32_t)__bfloat16_as_ushort(h2) | ((uint32_t)__bfloat16_as_ushort(h3) << 16);
        ub[i * 32 + l] = hv;
        float4 o2;
        o2.x = fxc * xc[i].x; o2.y = fxc * xc[i].y;
        o2.z = fxc * xc[i].z; o2.w = fxc * xc[i].w;
        o2p[i * 32 + l] = o2;
    }
    if (l == 0){
        g_cu2[row] = s * s * sn2;
        g_x2c[row] = py2;
    }
}

// ------------------------------------------------------------------
// Kernel 3: bf16 HMMA GEMM, BN=128, 2 CTAs/SM; fp16 epilogue stores.
// Trailing mainloop barrier removed (3-stage: prefetch never targets
// the stage being read; next iter's post-wait barrier orders reads).
// ------------------------------------------------------------------
#define BM 128
#define BN 128
#define BK 64
#define A_BYTES (BM*BK*2)
#define B_BYTES (BN*BK*2)
#define STAGE_BYTES (A_BYTES + B_BYTES)
#define NSTAGE 3
#define SM_TOT (NSTAGE * STAGE_BYTES)
#define NKT (KTOT / BK)

__global__ void __launch_bounds__(256, 2) gemm_mma(int row0){
    extern __shared__ __align__(128) char sm[];
    uint32_t sb = s2u(sm);
    int tid = threadIdx.x;
    int wid = tid >> 5, lane = tid & 31;
    int m0 = row0 + blockIdx.y * BM;
    int n0 = blockIdx.x * BN;
    int wm = wid & 1;
    int wn = wid >> 1;

    const char* gA = (const char*)g_ub;
    const char* gB = (const char*)g_zb;

    float acc[4][4][4];
#pragma unroll
    for (int i=0;i<4;i++)
#pragma unroll
        for (int j=0;j<4;j++)
#pragma unroll
            for (int k=0;k<4;k++) acc[i][j][k] = 0.f;

    int lr = tid >> 3;
    int lc = tid & 7;

#define LOAD_STAGE(s, kt) do {                                                 \
        uint32_t base_ = sb + (s) * STAGE_BYTES;                               \
        size_t k0_ = (size_t)(kt) * BK;                                        \
        _Pragma("unroll")                                                      \
        for (int it = 0; it < 4; it++){                                        \
            int r_ = it * 32 + lr;                                             \
            uint32_t so_ = base_ + r_ * 128 + ((lc ^ (r_ & 7)) << 4);          \
            cp16(so_, gA + ((size_t)(m0 + r_) * KTOT + k0_) * 2 + (lc << 4));  \
        }                                                                      \
        _Pragma("unroll")                                                      \
        for (int it = 0; it < 4; it++){                                        \
            int r_ = it * 32 + lr;                                             \
            uint32_t so_ = base_ + A_BYTES + r_ * 128 + ((lc ^ (r_ & 7)) << 4);\
            cp16(so_, gB + ((size_t)(n0 + r_) * KTOT + k0_) * 2 + (lc << 4));  \
        }                                                                      \
    } while (0)

    LOAD_STAGE(0, 0); cp_commit();
    LOAD_STAGE(1, 1); cp_commit();

    int lrow = lane & 15;
    int khalf = lane >> 4;

#pragma unroll 1
    for (int kt = 0; kt < NKT; kt++){
        cp_wait<1>();
        __syncthreads();        // orders all threads' stage-kt data visible
        uint32_t aBase = sb + (kt % 3) * STAGE_BYTES;
        uint32_t bBase = aBase + A_BYTES;
#pragma unroll
        for (int ks = 0; ks < 4; ks++){
            int c16 = ks * 2 + khalf;
            uint32_t a[4][4], bb[2][4];
#pragma unroll
            for (int i = 0; i < 4; i++){
                int row = wm * 64 + i * 16 + lrow;
                ldsm4(a[i], aBase + row * 128 + ((c16 ^ (row & 7)) << 4));
            }
#pragma unroll
            for (int j = 0; j < 2; j++){
                int row = wn * 32 + j * 16 + lrow;
                ldsm4(bb[j], bBase + row * 128 + ((c16 ^ (row & 7)) << 4));
            }
#pragma unroll
            for (int mi = 0; mi < 4; mi++)
#pragma unroll
                for (int ni = 0; ni < 4; ni++)
                    mma16816(acc[mi][ni], a[mi], bb[ni >> 1][ni & 1], bb[ni >> 1][(ni & 1) + 2]);
        }
        // prefetch targets stage (kt+2)%3 != (kt)%3 and != (kt+1)%3's reader
        // conflict window; no trailing barrier needed with 3 stages.
        if (kt + 2 < NKT){ LOAD_STAGE((kt + 2) % 3, kt + 2); }
        cp_commit();
    }

    int erow = lane >> 2;
    int ecol = (lane & 3) * 2;
#pragma unroll
    for (int mi = 0; mi < 4; mi++){
#pragma unroll
        for (int ni = 0; ni < 4; ni++){
            int r = m0 + wm * 64 + mi * 16 + erow;
            int c = n0 + wn * 32 + ni * 8 + ecol;
            __half* p = g_innh + (size_t)r * DIM + c;
            *(__half2*)p             = __floats2half2_rn(acc[mi][ni][0], acc[mi][ni][1]);
            *(__half2*)(p + 8 * DIM) = __floats2half2_rn(acc[mi][ni][2], acc[mi][ni][3]);
        }
    }
}

// ------------------------------------------------------------------
// Kernel 4: warp-per-row epilogue (chunked), o1 only, fp16 inner
// ------------------------------------------------------------------
__global__ void __launch_bounds__(256) finish_rows(const float* __restrict__ xc_g,
                                                   const float* __restrict__ alpha_p,
                                                   const float* __restrict__ step_p,
                                                   float* __restrict__ out,
                                                   int row0){
    int row = row0 + blockIdx.x * 8 + (threadIdx.x >> 5);
    int l   = threadIdx.x & 31;
    const uint2* in2 = (const uint2*)(g_innh + (size_t)row * DIM);
    const float4* xc4 = (const float4*)(xc_g + (size_t)row * DIM);
    const float4* c14 = (const float4*)g_c1;
    const float4* c24 = (const float4*)g_c2;
    const float4* s24 = (const float4*)g_s2;

    float cu2 = g_cu2[row], x2 = g_x2c[row];
    float invdn = f_rcp(fmaxf(1.f - cu2, EPSF));
    float op = 1.f + cu2;

    float w[16], xcv[16];
    float pw2 = 0.f, pxw = 0.f;
#pragma unroll
    for (int i = 0; i < 4; i++){
        int c4 = i * 32 + l;
        uint2 hv = in2[c4];
        float2 f01 = __half22float2(*(__half2*)&hv.x);
        float2 f23 = __half22float2(*(__half2*)&hv.y);
        float4 xv = xc4[c4], a = c14[c4], b = c24[c4], sv = s24[c4];
        float t0 = (f01.x * a.x - op * b.x) * invdn;
        float t1 = (f01.y * a.y - op * b.y) * invdn;
        float t2 = (f23.x * a.z - op * b.z) * invdn;
        float t3 = (f23.y * a.w - op * b.w) * invdn;
        float w0 = sinh_asinh(t0, sv.x), w1 = sinh_asinh(t1, sv.y);
        float w2 = sinh_asinh(t2, sv.z), w3 = sinh_asinh(t3, sv.w);
        w[i*4+0]=w0; w[i*4+1]=w1; w[i*4+2]=w2; w[i*4+3]=w3;
        xcv[i*4+0]=xv.x; xcv[i*4+1]=xv.y; xcv[i*4+2]=xv.z; xcv[i*4+3]=xv.w;
        pw2 = fmaf(w0,w0, fmaf(w1,w1, fmaf(w2,w2, fmaf(w3,w3, pw2))));
        pxw = fmaf(xv.x,w0, fmaf(xv.y,w1, fmaf(xv.z,w2, fmaf(xv.w,w3, pxw))));
    }
#pragma unroll
    for (int o = 16; o; o >>= 1){
        pw2 += __shfl_xor_sync(0xffffffffu, pw2, o);
        pxw += __shfl_xor_sync(0xffffffffu, pxw, o);
    }
    float w2s = pw2, xw = pxw;

    float gg  = 1.f + f_sqrt(1.f + w2s);
    float rg  = f_rcp(gg);
    float yn  = f_sqrt(fmaxf(w2s * rg * rg, EPSF));
    float kv  = atanh_f(fminf(yn, CLIPA)) * f_rcp(yn);
    float step = sigmoid_f(step_p[0]);
    float m0s = step * kv * rg;
    float un  = f_sqrt(fmaxf(m0s * m0s * w2s, EPSF));
    float lam = 2.f * f_rcp(fmaxf(1.f - x2, EPSF));
    float mt  = tanh_f(0.5f * lam * un) * m0s * f_rcp(un);

    float t2s = mt * mt * w2s;
    float xt  = mt * xw;
    float pp  = 1.f + 2.f * xt + t2s;
    float qq  = 1.f - x2;
    float id2 = f_rcp(fmaxf(1.f + 2.f * xt + x2 * t2s, EPSF));
    float a1  = pp * id2, b1 = qq * mt * id2;

    float nxu2 = a1*a1*x2 + 2.f*a1*b1*xw + b1*b1*w2s;
    float nxu  = f_sqrt(fmaxf(nxu2, EPSF));
    float fxu  = (nxu > MAXN) ? MAXN * f_rcp(nxu) : 1.f;
    a1 *= fxu; b1 *= fxu;
    float nxup = fminf(nxu, MAXN);

    float nxc  = f_sqrt(fmaxf(x2, EPSF));
    float fxc  = (nxc > MAXN) ? MAXN * f_rcp(nxc) : 1.f;
    float nxcp = fminf(nxc, MAXN);

    float aa  = sigmoid_f(alpha_p[0]);
    float th1 = tanh_f(aa * atanh_f(fminf(nxcp, CLIPA)));
    float A1  = th1 * f_rcp(nxcp) * fxc;
    float th2 = tanh_f((1.f - aa) * atanh_f(fminf(nxup, CLIPA)));
    float r2  = th2 * f_rcp(nxup);
    float A2  = r2 * a1, B2 = r2 * b1;

    float x2m = th1 * th1, y2m = th2 * th2;
    float xym = A1 * (A2 * x2 + B2 * xw);
    float P   = 1.f + 2.f * xym + y2m;
    float Q   = 1.f - x2m;
    float id3 = f_rcp(fmaxf(1.f + 2.f * xym + x2m * y2m, EPSF));
    float CA  = (P * A1 + Q * A2) * id3;
    float CB  = (Q * B2) * id3;

    float nn2 = CA*CA*x2 + 2.f*CA*CB*xw + CB*CB*w2s;
    float nn  = f_sqrt(fmaxf(nn2, EPSF));
    float fo  = (nn > MAXN) ? MAXN * f_rcp(nn) : 1.f;
    CA *= fo; CB *= fo;

    float4* o1p = (float4*)(out + (size_t)row * DIM);
#pragma unroll
    for (int i = 0; i < 4; i++){
        int c4 = i * 32 + l;
        float4 o1;
        o1.x = CA*xcv[i*4+0] + CB*w[i*4+0];
        o1.y = CA*xcv[i*4+1] + CB*w[i*4+1];
        o1.z = CA*xcv[i*4+2] + CB*w[i*4+2];
        o1.w = CA*xcv[i*4+3] + CB*w[i*4+3];
        o1p[c4] = o1;
    }
}

// ------------------------------------------------------------------
// Launch: 3 streams, 6 uneven chunks (R15 graph, finer granularity)
// ------------------------------------------------------------------
extern "C" void kernel_launch(void* const* d_in, const int* in_sizes, int n_in,
                              void* d_out, int out_size) {
    const float* xc    = (const float*)d_in[0];
    const float* xp    = (const float*)d_in[1];
    const float* z     = (const float*)d_in[2];
    const float* bias  = (const float*)d_in[3];
    const float* alpha = (const float*)d_in[4];
    const float* stepz = (const float*)d_in[5];
    float* out = (float*)d_out;

    static cudaStream_t s1, s2, s3;
    static cudaEvent_t eRoot, eC, eP[NCHUNK], eG[NCHUNK], eJ1, eJ2, eJ3;
    static int inited = 0;
    if (!inited){
        cudaStreamCreateWithFlags(&s1, cudaStreamNonBlocking);
        cudaStreamCreateWithFlags(&s2, cudaStreamNonBlocking);
        cudaStreamCreateWithFlags(&s3, cudaStreamNonBlocking);
        cudaEventCreateWithFlags(&eRoot, cudaEventDisableTiming);
        cudaEventCreateWithFlags(&eC, cudaEventDisableTiming);
        for (int m = 0; m < NCHUNK; m++){
            cudaEventCreateWithFlags(&eP[m], cudaEventDisableTiming);
            cudaEventCreateWithFlags(&eG[m], cudaEventDisableTiming);
        }
        cudaEventCreateWithFlags(&eJ1, cudaEventDisableTiming);
        cudaEventCreateWithFlags(&eJ2, cudaEventDisableTiming);
        cudaEventCreateWithFlags(&eJ3, cudaEventDisableTiming);
        cudaFuncSetAttribute(gemm_mma, cudaFuncAttributeMaxDynamicSharedMemorySize, SM_TOT);
        inited = 1;
    }

    // fork
    cudaEventRecord(eRoot, 0);
    cudaStreamWaitEvent(s1, eRoot, 0);
    cudaStreamWaitEvent(s2, eRoot, 0);
    cudaStreamWaitEvent(s3, eRoot, 0);

    // s3: column prep off the gemm stream
    prep_cols<<<DIM, 128, 0, s3>>>(z, bias);
    cudaEventRecord(eC, s3);
    cudaStreamWaitEvent(s1, eC, 0);

    // s2: row prep per chunk (also writes o2)
    for (int m = 0; m < NCHUNK; m++){
        int r0 = CHUNK_OFF[m], nr = CHUNK_OFF[m + 1] - r0;
        prep_rows<<<nr / 8, 256, 0, s2>>>(xc, xp, out, r0);
        cudaEventRecord(eP[m], s2);
    }

    // s1: gemm per chunk
    for (int m = 0; m < NCHUNK; m++){
        int r0 = CHUNK_OFF[m], nr = CHUNK_OFF[m + 1] - r0;
        cudaStreamWaitEvent(s1, eP[m], 0);
        gemm_mma<<<dim3(DIM / BN, nr / BM), 256, SM_TOT, s1>>>(r0);
        cudaEventRecord(eG[m], s1);
    }

    // s3: finish per chunk (o1 only)
    for (int m = 0; m < NCHUNK; m++){
        int r0 = CHUNK_OFF[m], nr = CHUNK_OFF[m + 1] - r0;
        cudaStreamWaitEvent(s3, eG[m], 0);
        finish_rows<<<nr / 8, 256, 0, s3>>>(xc, alpha, stepz, out, r0);
    }

    // join
    cudaEventRecord(eJ1, s1);
    cudaEventRecord(eJ2, s2);
    cudaEventRecord(eJ3, s3);
    cudaStreamWaitEvent(0, eJ1, 0);
    cudaStreamWaitEvent(0, eJ2, 0);
    cudaStreamWaitEvent(0, eJ3, 0);
}